// round 1
// baseline (speedup 1.0000x reference)
#include <cuda_runtime.h>

// ScaledDotProductAttention: B=4 H=16 S=2048 DK=128, fp32, causal mask.
// Output buffer = concat( output[B,H,S,DK], attn[B,H,S,S] ) in fp32.
//
// Two-pass plan:
//  pass 1: L[bh,row] = sum_{k<=row} exp(score)   (scores small, no max needed)
//  pass 2: recompute scores, p = exp(score)/L -> write attn; O += p @ V -> write output
//          upper-triangle attn tiles are zero-filled (d_out is poisoned).

namespace {
constexpr int BHn = 64;      // B*H
constexpr int Sn  = 2048;
constexpr int DKn = 128;
constexpr int BM  = 64;      // query tile
constexpr int BN  = 64;      // key tile
constexpr int NT  = Sn / BN; // 32 key tiles
constexpr int THREADS = 256;
constexpr int TSTR = 68;     // transposed [dk][row] tile stride (mult of 4, pad vs 64)
constexpr int VSTR = 132;    // V row-major [key][dk] stride (mult of 4, pad vs 128)
constexpr int PSTR = 68;     // P transposed [key][row] stride
constexpr float SCALE = 0.08838834764831845f; // 1/sqrt(128)
}

__device__ float g_L[BHn * Sn];

extern __shared__ float smem[];

// ---------------------------------------------------------------------------
// Pass 1: per-row sum of exp(scaled score) over the causal range.
// ---------------------------------------------------------------------------
__global__ __launch_bounds__(THREADS) void rowsum_kernel(
    const float* __restrict__ q, const float* __restrict__ k) {
  float* Qt   = smem;                 // [DKn][TSTR]
  float* Kt   = Qt + DKn * TSTR;      // [DKn][TSTR]
  float* Lrow = Kt + DKn * TSTR;      // [BM]

  const int it  = blockIdx.x;
  const int bh  = blockIdx.y;
  const int tid = threadIdx.x;

  const float* qb = q + ((size_t)bh * Sn + (size_t)it * BM) * DKn;
  const float* kb = k + (size_t)bh * Sn * DKn;

  // Load Q tile transposed: Qt[dk][row]
  for (int idx = tid; idx < BM * (DKn / 4); idx += THREADS) {
    int row = idx >> 5;   // DKn/4 == 32 float4 per row
    int c4  = idx & 31;
    float4 t = reinterpret_cast<const float4*>(qb + (size_t)row * DKn)[c4];
    Qt[(4 * c4 + 0) * TSTR + row] = t.x;
    Qt[(4 * c4 + 1) * TSTR + row] = t.y;
    Qt[(4 * c4 + 2) * TSTR + row] = t.z;
    Qt[(4 * c4 + 3) * TSTR + row] = t.w;
  }
  if (tid < BM) Lrow[tid] = 0.0f;

  const int tx = tid & 15, ty = tid >> 4;
  const int r0 = ty * 4, c0 = tx * 4;
  float lsum[4] = {0.f, 0.f, 0.f, 0.f};

  for (int jt = 0; jt <= it; ++jt) {
    __syncthreads();
    // Load K tile transposed: Kt[dk][key]
    for (int idx = tid; idx < BN * (DKn / 4); idx += THREADS) {
      int row = idx >> 5;
      int c4  = idx & 31;
      float4 t = reinterpret_cast<const float4*>(kb + (size_t)(jt * BN + row) * DKn)[c4];
      Kt[(4 * c4 + 0) * TSTR + row] = t.x;
      Kt[(4 * c4 + 1) * TSTR + row] = t.y;
      Kt[(4 * c4 + 2) * TSTR + row] = t.z;
      Kt[(4 * c4 + 3) * TSTR + row] = t.w;
    }
    __syncthreads();

    float acc[4][4] = {};
#pragma unroll 8
    for (int kk = 0; kk < DKn; ++kk) {
      float4 a = *reinterpret_cast<const float4*>(Qt + kk * TSTR + r0);
      float4 b = *reinterpret_cast<const float4*>(Kt + kk * TSTR + c0);
      float av[4] = {a.x, a.y, a.z, a.w};
      float bv[4] = {b.x, b.y, b.z, b.w};
#pragma unroll
      for (int i = 0; i < 4; ++i)
#pragma unroll
        for (int j = 0; j < 4; ++j) acc[i][j] = fmaf(av[i], bv[j], acc[i][j]);
    }

    const bool diag = (jt == it);
#pragma unroll
    for (int i = 0; i < 4; ++i)
#pragma unroll
      for (int j = 0; j < 4; ++j)
        if (!diag || (c0 + j) <= (r0 + i))
          lsum[i] += __expf(acc[i][j] * SCALE);
  }

  __syncthreads();
#pragma unroll
  for (int i = 0; i < 4; ++i) atomicAdd(&Lrow[r0 + i], lsum[i]);
  __syncthreads();
  if (tid < BM) g_L[(size_t)bh * Sn + (size_t)it * BM + tid] = Lrow[tid];
}

// ---------------------------------------------------------------------------
// Pass 2: recompute scores, write normalized attn, accumulate O = P @ V.
// ---------------------------------------------------------------------------
__global__ __launch_bounds__(THREADS) void attn_out_kernel(
    const float* __restrict__ q, const float* __restrict__ k,
    const float* __restrict__ v, float* __restrict__ out,
    float* __restrict__ attn, int write_attn) {
  float* Qt = smem;                  // [DKn][TSTR]
  float* KV = Qt + DKn * TSTR;       // K transposed [DKn][TSTR] OR V row-major [BN][VSTR]
  float* Pt = KV + DKn * TSTR;       // [BN keys][PSTR rows]
  float* Ls = Pt + BM * PSTR;        // [BM]

  const int it  = blockIdx.x;
  const int bh  = blockIdx.y;
  const int tid = threadIdx.x;
  const size_t qrow0 = (size_t)it * BM;

  const float* qb = q + ((size_t)bh * Sn + qrow0) * DKn;
  const float* kb = k + (size_t)bh * Sn * DKn;
  const float* vb = v + (size_t)bh * Sn * DKn;

  for (int idx = tid; idx < BM * (DKn / 4); idx += THREADS) {
    int row = idx >> 5;
    int c4  = idx & 31;
    float4 t = reinterpret_cast<const float4*>(qb + (size_t)row * DKn)[c4];
    Qt[(4 * c4 + 0) * TSTR + row] = t.x;
    Qt[(4 * c4 + 1) * TSTR + row] = t.y;
    Qt[(4 * c4 + 2) * TSTR + row] = t.z;
    Qt[(4 * c4 + 3) * TSTR + row] = t.w;
  }
  if (tid < BM) Ls[tid] = g_L[(size_t)bh * Sn + qrow0 + tid];
  __syncthreads();

  const int tx = tid & 15, ty = tid >> 4;
  const int r0 = ty * 4, c0 = tx * 4;

  float invL[4];
#pragma unroll
  for (int i = 0; i < 4; ++i) invL[i] = 1.0f / Ls[r0 + i];

  float oacc[4][8] = {};

  for (int jt = 0; jt <= it; ++jt) {
    __syncthreads();
    // K tile transposed into KV
    for (int idx = tid; idx < BN * (DKn / 4); idx += THREADS) {
      int row = idx >> 5;
      int c4  = idx & 31;
      float4 t = reinterpret_cast<const float4*>(kb + (size_t)(jt * BN + row) * DKn)[c4];
      KV[(4 * c4 + 0) * TSTR + row] = t.x;
      KV[(4 * c4 + 1) * TSTR + row] = t.y;
      KV[(4 * c4 + 2) * TSTR + row] = t.z;
      KV[(4 * c4 + 3) * TSTR + row] = t.w;
    }
    __syncthreads();

    float acc[4][4] = {};
#pragma unroll 8
    for (int kk = 0; kk < DKn; ++kk) {
      float4 a = *reinterpret_cast<const float4*>(Qt + kk * TSTR + r0);
      float4 b = *reinterpret_cast<const float4*>(KV + kk * TSTR + c0);
      float av[4] = {a.x, a.y, a.z, a.w};
      float bv[4] = {b.x, b.y, b.z, b.w};
#pragma unroll
      for (int i = 0; i < 4; ++i)
#pragma unroll
        for (int j = 0; j < 4; ++j) acc[i][j] = fmaf(av[i], bv[j], acc[i][j]);
    }

    const bool diag = (jt == it);
    float p[4][4];
#pragma unroll
    for (int i = 0; i < 4; ++i)
#pragma unroll
      for (int j = 0; j < 4; ++j) {
        bool ok = !diag || ((c0 + j) <= (r0 + i));
        p[i][j] = ok ? __expf(acc[i][j] * SCALE) * invL[i] : 0.0f;
      }

    if (write_attn) {
#pragma unroll
      for (int i = 0; i < 4; ++i) {
        float4 pv = make_float4(p[i][0], p[i][1], p[i][2], p[i][3]);
        float* dst = attn + ((size_t)bh * Sn + (qrow0 + r0 + i)) * Sn +
                     (size_t)jt * BN + c0;
        *reinterpret_cast<float4*>(dst) = pv;
      }
    }
    // Stage P transposed: Pt[key][row]
#pragma unroll
    for (int i = 0; i < 4; ++i)
#pragma unroll
      for (int j = 0; j < 4; ++j) Pt[(c0 + j) * PSTR + (r0 + i)] = p[i][j];

    __syncthreads();  // all K reads + Pt writes done -> safe to overwrite KV with V
    for (int idx = tid; idx < BN * (DKn / 4); idx += THREADS) {
      int row = idx >> 5;
      int c4  = idx & 31;
      float4 t = reinterpret_cast<const float4*>(vb + (size_t)(jt * BN + row) * DKn)[c4];
      reinterpret_cast<float4*>(KV + row * VSTR)[c4] = t;
    }
    __syncthreads();

    // O[4 rows][8 cols] += Pt^T @ V ; rows 4*ty, cols 8*tx
#pragma unroll 4
    for (int kk2 = 0; kk2 < BN; ++kk2) {
      float4 pa  = *reinterpret_cast<const float4*>(Pt + kk2 * PSTR + r0);
      float4 vb0 = *reinterpret_cast<const float4*>(KV + kk2 * VSTR + 8 * tx);
      float4 vb1 = *reinterpret_cast<const float4*>(KV + kk2 * VSTR + 8 * tx + 4);
      float pv[4] = {pa.x, pa.y, pa.z, pa.w};
      float vv[8] = {vb0.x, vb0.y, vb0.z, vb0.w, vb1.x, vb1.y, vb1.z, vb1.w};
#pragma unroll
      for (int i = 0; i < 4; ++i)
#pragma unroll
        for (int j = 0; j < 8; ++j) oacc[i][j] = fmaf(pv[i], vv[j], oacc[i][j]);
    }
  }

  // Zero-fill upper-triangle attn tiles (output buffer is poisoned).
  if (write_attn) {
    float4 z = make_float4(0.f, 0.f, 0.f, 0.f);
    for (int jt = it + 1; jt < NT; ++jt) {
#pragma unroll
      for (int i = 0; i < 4; ++i) {
        float* dst = attn + ((size_t)bh * Sn + (qrow0 + r0 + i)) * Sn +
                     (size_t)jt * BN + c0;
        *reinterpret_cast<float4*>(dst) = z;
      }
    }
  }

  // Write O: rows 4*ty + i, cols 8*tx .. 8*tx+7
#pragma unroll
  for (int i = 0; i < 4; ++i) {
    float* orow = out + ((size_t)bh * Sn + qrow0 + r0 + i) * DKn + 8 * tx;
    float4 o0 = make_float4(oacc[i][0], oacc[i][1], oacc[i][2], oacc[i][3]);
    float4 o1 = make_float4(oacc[i][4], oacc[i][5], oacc[i][6], oacc[i][7]);
    reinterpret_cast<float4*>(orow)[0] = o0;
    reinterpret_cast<float4*>(orow)[1] = o1;
  }
}

extern "C" void kernel_launch(void* const* d_in, const int* in_sizes, int n_in,
                              void* d_out, int out_size) {
  const float* q = (const float*)d_in[0];
  const float* k = (const float*)d_in[1];
  const float* v = (const float*)d_in[2];
  // d_in[3] is the causal mask (tril) — implied by k<=q, not read.
  (void)in_sizes; (void)n_in;

  float* out = (float*)d_out;
  const long long OUT_ELEMS  = (long long)BHn * Sn * DKn;   // 16,777,216
  const long long ATTN_ELEMS = (long long)BHn * Sn * Sn;    // 268,435,456
  float* attn = nullptr;
  int write_attn = 0;
  if ((long long)out_size >= OUT_ELEMS + ATTN_ELEMS) {
    attn = out + OUT_ELEMS;
    write_attn = 1;
  }

  const int smemA = (2 * DKn * TSTR + BM) * (int)sizeof(float);               // ~69.9 KB
  const int smemB = (2 * DKn * TSTR + BM * PSTR + BM) * (int)sizeof(float);   // ~87.3 KB
  cudaFuncSetAttribute(rowsum_kernel, cudaFuncAttributeMaxDynamicSharedMemorySize, smemA);
  cudaFuncSetAttribute(attn_out_kernel, cudaFuncAttributeMaxDynamicSharedMemorySize, smemB);

  dim3 grid(NT, BHn);
  rowsum_kernel<<<grid, THREADS, smemA>>>(q, k);
  attn_out_kernel<<<grid, THREADS, smemB>>>(q, k, v, out, attn, write_attn);
}

// round 2
// speedup vs baseline: 2.0387x; 2.0387x over previous
#include <cuda_runtime.h>

// ScaledDotProductAttention: B=4 H=16 S=2048 DK=128, fp32, causal.
// d_out = concat( output[B,H,S,DK], attn[B,H,S,S] ), fp32.
//
// Kernel 1 (fused): per (bh, 128-row qtile), loop causal key tiles:
//   S = Q K^T (8x8 microtile SIMT), Pt~ = exp(S*scale) (masked),
//   write Pt~ (UNNORMALIZED) to attn, accumulate L (rowsum) and O~ += Pt~ V.
//   After loop: O = O~ / L, store L to g_L.
// Kernel 2: attn[row] *= 1/L[row] over causal region; zero upper triangle.

namespace {
constexpr int BHn = 64;
constexpr int Sn  = 2048;
constexpr int DKn = 128;
constexpr int BM  = 128;
constexpr int BN  = 128;
constexpr int NT  = Sn / BN;   // 16
constexpr int THREADS = 256;
constexpr int TSTR = 132;      // padded smem stride (floats)
constexpr float SCALE = 0.08838834764831845f;  // 1/sqrt(128)
}

__device__ float g_L[BHn * Sn];

extern __shared__ float smem[];

// Load a 128x128 fp32 tile row-major from global, store TRANSPOSED [col][TSTR]
// into smem via register 4x4 transpose (coalesced LDG.128, STS.128 at crossbar floor).
__device__ __forceinline__ void load_tile_transposed(
    const float* __restrict__ src, float* __restrict__ dst, int tid) {
#pragma unroll
  for (int t = 0; t < 4; ++t) {
    int blk = tid + t * 256;
    int rg = blk >> 5;   // row group (4 rows)
    int cg = blk & 31;   // col group (4 cols)
    const float* s0 = src + (size_t)(rg * 4) * DKn + cg * 4;
    float4 a = *(const float4*)(s0);
    float4 b = *(const float4*)(s0 + DKn);
    float4 c = *(const float4*)(s0 + 2 * DKn);
    float4 d = *(const float4*)(s0 + 3 * DKn);
    float* dbase = dst + rg * 4;
    *(float4*)(dbase + (size_t)(cg * 4 + 0) * TSTR) = make_float4(a.x, b.x, c.x, d.x);
    *(float4*)(dbase + (size_t)(cg * 4 + 1) * TSTR) = make_float4(a.y, b.y, c.y, d.y);
    *(float4*)(dbase + (size_t)(cg * 4 + 2) * TSTR) = make_float4(a.z, b.z, c.z, d.z);
    *(float4*)(dbase + (size_t)(cg * 4 + 3) * TSTR) = make_float4(a.w, b.w, c.w, d.w);
  }
}

// Load a 128x128 tile row-major into smem [row][TSTR] (no transpose).
__device__ __forceinline__ void load_tile_rowmajor(
    const float* __restrict__ src, float* __restrict__ dst, int tid) {
#pragma unroll
  for (int t = 0; t < 16; ++t) {
    int idx = tid + t * 256;
    int row = idx >> 5;
    int c4  = idx & 31;
    float4 x = *(const float4*)(src + (size_t)row * DKn + c4 * 4);
    *(float4*)(dst + (size_t)row * TSTR + c4 * 4) = x;
  }
}

__global__ __launch_bounds__(THREADS, 1) void fused_attn_kernel(
    const float* __restrict__ q, const float* __restrict__ k,
    const float* __restrict__ v, float* __restrict__ out,
    float* __restrict__ attn, int write_attn) {
  float* Qt   = smem;                  // [DKn][TSTR]  Q transposed (loaded once)
  float* KV   = Qt + DKn * TSTR;       // Kt [DKn][TSTR] then V [BN][TSTR]
  float* Pt   = KV + DKn * TSTR;       // [BN keys][TSTR rows]
  float* Lrow = Pt + (size_t)BN * TSTR;  // [BM]

  const int it  = blockIdx.x;
  const int bh  = blockIdx.y;
  const int tid = threadIdx.x;
  const size_t qrow0 = (size_t)it * BM;

  const float* qb = q + ((size_t)bh * Sn + qrow0) * DKn;
  const float* kb = k + (size_t)bh * Sn * DKn;
  const float* vb = v + (size_t)bh * Sn * DKn;

  load_tile_transposed(qb, Qt, tid);
  if (tid < BM) Lrow[tid] = 0.0f;

  const int tx = tid & 15, ty = tid >> 4;
  const int r0 = ty * 8, c0 = tx * 8;

  float o[8][8] = {};
  float lsum[8] = {};

  for (int jt = 0; jt <= it; ++jt) {
    __syncthreads();  // protect KV (K overwrite) & Pt vs previous PV readers
    load_tile_transposed(kb + (size_t)jt * BN * DKn, KV, tid);
    __syncthreads();

    // S = Q K^T : 8x8 per thread over 128 dk
    float s[8][8] = {};
#pragma unroll 8
    for (int kk = 0; kk < DKn; ++kk) {
      const float* qr = Qt + (size_t)kk * TSTR;
      const float* kr = KV + (size_t)kk * TSTR;
      float4 a0 = *(const float4*)(qr + r0);
      float4 a1 = *(const float4*)(qr + r0 + 4);
      float4 b0 = *(const float4*)(kr + c0);
      float4 b1 = *(const float4*)(kr + c0 + 4);
      float av[8] = {a0.x, a0.y, a0.z, a0.w, a1.x, a1.y, a1.z, a1.w};
      float bv[8] = {b0.x, b0.y, b0.z, b0.w, b1.x, b1.y, b1.z, b1.w};
#pragma unroll
      for (int i = 0; i < 8; ++i)
#pragma unroll
        for (int j = 0; j < 8; ++j) s[i][j] = fmaf(av[i], bv[j], s[i][j]);
    }

    // Pt~ = exp(masked), accumulate rowsums, write unnormalized attn
    const bool diag = (jt == it);
#pragma unroll
    for (int i = 0; i < 8; ++i) {
#pragma unroll
      for (int j = 0; j < 8; ++j) {
        bool ok = !diag || ((c0 + j) <= (r0 + i));
        float e = ok ? __expf(s[i][j] * SCALE) : 0.0f;
        s[i][j] = e;
        lsum[i] += e;
      }
    }

    if (write_attn) {
#pragma unroll
      for (int i = 0; i < 8; ++i) {
        float* dst = attn + ((size_t)bh * Sn + (qrow0 + r0 + i)) * Sn +
                     (size_t)jt * BN + c0;
        *(float4*)(dst)     = make_float4(s[i][0], s[i][1], s[i][2], s[i][3]);
        *(float4*)(dst + 4) = make_float4(s[i][4], s[i][5], s[i][6], s[i][7]);
      }
    }

    // Stage Pt transposed: Pt[key][row]
#pragma unroll
    for (int j = 0; j < 8; ++j) {
      float* pr = Pt + (size_t)(c0 + j) * TSTR + r0;
      *(float4*)(pr)     = make_float4(s[0][j], s[1][j], s[2][j], s[3][j]);
      *(float4*)(pr + 4) = make_float4(s[4][j], s[5][j], s[6][j], s[7][j]);
    }

    __syncthreads();  // Pt written, KV (K) reads done
    load_tile_rowmajor(vb + (size_t)jt * BN * DKn, KV, tid);
    __syncthreads();

    // O~ += Pt^T @ V over 128 keys
#pragma unroll 8
    for (int kk = 0; kk < BN; ++kk) {
      const float* pr = Pt + (size_t)kk * TSTR;
      const float* vr = KV + (size_t)kk * TSTR;
      float4 a0 = *(const float4*)(pr + r0);
      float4 a1 = *(const float4*)(pr + r0 + 4);
      float4 b0 = *(const float4*)(vr + c0);
      float4 b1 = *(const float4*)(vr + c0 + 4);
      float av[8] = {a0.x, a0.y, a0.z, a0.w, a1.x, a1.y, a1.z, a1.w};
      float bv[8] = {b0.x, b0.y, b0.z, b0.w, b1.x, b1.y, b1.z, b1.w};
#pragma unroll
      for (int i = 0; i < 8; ++i)
#pragma unroll
        for (int j = 0; j < 8; ++j) o[i][j] = fmaf(av[i], bv[j], o[i][j]);
    }
  }

  // Reduce rowsums, normalize O, write out
  __syncthreads();
#pragma unroll
  for (int i = 0; i < 8; ++i) atomicAdd(&Lrow[r0 + i], lsum[i]);
  __syncthreads();

  if (tid < BM) g_L[(size_t)bh * Sn + qrow0 + tid] = Lrow[tid];

#pragma unroll
  for (int i = 0; i < 8; ++i) {
    float inv = 1.0f / Lrow[r0 + i];
    float* orow = out + ((size_t)bh * Sn + qrow0 + r0 + i) * DKn + c0;
    *(float4*)(orow) =
        make_float4(o[i][0] * inv, o[i][1] * inv, o[i][2] * inv, o[i][3] * inv);
    *(float4*)(orow + 4) =
        make_float4(o[i][4] * inv, o[i][5] * inv, o[i][6] * inv, o[i][7] * inv);
  }
}

// Normalize attn rows by 1/L; zero the strict upper triangle (write-only there).
__global__ __launch_bounds__(256) void norm_attn_kernel(float* __restrict__ attn) {
  const int bh  = blockIdx.z;
  const int row = blockIdx.y;
  const int c4  = blockIdx.x * 256 + threadIdx.x;  // float4 index, 0..511
  const int col = c4 * 4;

  float4* p = (float4*)(attn + ((size_t)bh * Sn + row) * Sn) + c4;
  if (col > row) {
    *p = make_float4(0.f, 0.f, 0.f, 0.f);
    return;
  }
  const float inv = 1.0f / g_L[(size_t)bh * Sn + row];
  float4 a = *p;
  if (col + 3 <= row) {
    a.x *= inv; a.y *= inv; a.z *= inv; a.w *= inv;
  } else {
    a.x = (col + 0 <= row) ? a.x * inv : 0.f;
    a.y = (col + 1 <= row) ? a.y * inv : 0.f;
    a.z = (col + 2 <= row) ? a.z * inv : 0.f;
    a.w = (col + 3 <= row) ? a.w * inv : 0.f;
  }
  *p = a;
}

extern "C" void kernel_launch(void* const* d_in, const int* in_sizes, int n_in,
                              void* d_out, int out_size) {
  const float* q = (const float*)d_in[0];
  const float* k = (const float*)d_in[1];
  const float* v = (const float*)d_in[2];
  (void)in_sizes; (void)n_in;  // d_in[3] = tril mask, implied by k<=q

  float* out = (float*)d_out;
  const long long OUT_ELEMS  = (long long)BHn * Sn * DKn;
  const long long ATTN_ELEMS = (long long)BHn * Sn * Sn;
  float* attn = nullptr;
  int write_attn = 0;
  if ((long long)out_size >= OUT_ELEMS + ATTN_ELEMS) {
    attn = out + OUT_ELEMS;
    write_attn = 1;
  }

  const int smem1 = (3 * DKn * TSTR + BM) * (int)sizeof(float);  // ~203 KB
  cudaFuncSetAttribute(fused_attn_kernel,
                       cudaFuncAttributeMaxDynamicSharedMemorySize, smem1);

  dim3 grid1(NT, BHn);
  fused_attn_kernel<<<grid1, THREADS, smem1>>>(q, k, v, out, attn, write_attn);

  if (write_attn) {
    dim3 grid2(Sn / (4 * 256), Sn, BHn);  // (2, 2048, 64)
    norm_attn_kernel<<<grid2, 256>>>(attn);
  }
}

// round 5
// speedup vs baseline: 4.4910x; 2.2029x over previous
#include <cuda_runtime.h>
#include <cuda_bf16.h>
#include <cstdint>

// ScaledDotProductAttention B=4 H=16 S=2048 DK=128 fp32 causal.
// d_out = concat( output[B,H,S,DK], attn[B,H,S,S] ).
// mma.sync bf16 hi/lo split-precision implementation (no tcgen05: harness
// ptxas target is plain sm_103, 'a'-features unavailable).

namespace {
constexpr int BHn = 64, Sn = 2048, DKn = 128, NT = 16;
constexpr int THREADS = 256;
constexpr float SCALE = 0.08838834764831845f;  // 1/sqrt(128)

// smem byte offsets (three 64KB tile pairs + Lrow)
constexpr int SM_QH = 0, SM_QL = 32768;
constexpr int SM_KVH = 65536, SM_KVL = 98304;
constexpr int SM_PH = 131072, SM_PL = 163840;
constexpr int SM_L = 196608;
constexpr int SMEM_TOTAL = SM_L + 512;
}

__device__ __nv_bfloat16 g_qh[(size_t)BHn * Sn * DKn];
__device__ __nv_bfloat16 g_ql[(size_t)BHn * Sn * DKn];
__device__ __nv_bfloat16 g_kh[(size_t)BHn * Sn * DKn];
__device__ __nv_bfloat16 g_kl[(size_t)BHn * Sn * DKn];
__device__ __nv_bfloat16 g_vh[(size_t)BHn * Sn * DKn];
__device__ __nv_bfloat16 g_vl[(size_t)BHn * Sn * DKn];
__device__ float g_L[(size_t)BHn * Sn];

// ---------------- helpers ----------------
__device__ __forceinline__ uint32_t smem_u32(const void* p) {
  uint32_t a;
  asm("{ .reg .u64 t; cvta.to.shared.u64 t, %1; cvt.u32.u64 %0, t; }" : "=r"(a) : "l"(p));
  return a;
}
__device__ __forceinline__ void cp16(uint32_t saddr, const void* g) {
  asm volatile("cp.async.cg.shared.global [%0], [%1], 16;" ::"r"(saddr), "l"(g));
}
__device__ __forceinline__ void cp_commit() { asm volatile("cp.async.commit_group;" ::: "memory"); }
__device__ __forceinline__ void cp_wait0() { asm volatile("cp.async.wait_group 0;" ::: "memory"); }

__device__ __forceinline__ void ldsm4(uint32_t addr, uint32_t* r) {
  asm volatile("ldmatrix.sync.aligned.m8n8.x4.shared.b16 {%0,%1,%2,%3}, [%4];"
               : "=r"(r[0]), "=r"(r[1]), "=r"(r[2]), "=r"(r[3]) : "r"(addr));
}
__device__ __forceinline__ void ldsm4t(uint32_t addr, uint32_t* r) {
  asm volatile("ldmatrix.sync.aligned.m8n8.x4.trans.shared.b16 {%0,%1,%2,%3}, [%4];"
               : "=r"(r[0]), "=r"(r[1]), "=r"(r[2]), "=r"(r[3]) : "r"(addr));
}
__device__ __forceinline__ void mma16816(float* d, const uint32_t* a, const uint32_t* b) {
  asm volatile(
      "mma.sync.aligned.m16n8k16.row.col.f32.bf16.bf16.f32 "
      "{%0,%1,%2,%3}, {%4,%5,%6,%7}, {%8,%9}, {%0,%1,%2,%3};"
      : "+f"(d[0]), "+f"(d[1]), "+f"(d[2]), "+f"(d[3])
      : "r"(a[0]), "r"(a[1]), "r"(a[2]), "r"(a[3]), "r"(b[0]), "r"(b[1]));
}
__device__ __forceinline__ uint32_t packbf2(float a, float b) {
  __nv_bfloat162 t;
  t.x = __float2bfloat16(a);
  t.y = __float2bfloat16(b);
  return *reinterpret_cast<uint32_t*>(&t);
}

// SW128 blocked-atom byte offset for 128x128 bf16 tile.
// atom = 8 rows x 64 cols (1024B); atom index = (c>>6)*16 + (r>>3).
__device__ __forceinline__ uint32_t tile_off(int r, int c) {
  uint32_t byte =
      ((uint32_t)(((c >> 6) << 4) + (r >> 3)) << 10) + ((r & 7) << 7) + ((c & 63) << 1);
  return byte ^ ((byte >> 3) & 0x70);
}

// load 128x128 bf16 row-major tile (stride 128) into blocked-atom smem
__device__ __forceinline__ void load_tile(const __nv_bfloat16* __restrict__ src, uint32_t dst,
                                          int tid) {
#pragma unroll
  for (int t = 0; t < 8; ++t) {
    int i = tid + t * THREADS;
    int r = i >> 4, c8 = (i & 15) * 8;
    cp16(dst + tile_off(r, c8), src + (size_t)r * DKn + c8);
  }
}

// ---------------- precompute: bf16 hi/lo split ----------------
__global__ __launch_bounds__(256) void split_kernel(const float* __restrict__ src, int which) {
  __nv_bfloat16* hi = which == 0 ? g_qh : (which == 1 ? g_kh : g_vh);
  __nv_bfloat16* lo = which == 0 ? g_ql : (which == 1 ? g_kl : g_vl);
  size_t i = (size_t)blockIdx.x * 256 + threadIdx.x;  // float4 index
  float4 x = reinterpret_cast<const float4*>(src)[i];
  float v[4] = {x.x, x.y, x.z, x.w};
  uint32_t hw[2], lw[2];
#pragma unroll
  for (int p = 0; p < 2; ++p) {
    float a = v[2 * p], b = v[2 * p + 1];
    __nv_bfloat16 ha = __float2bfloat16(a), hb = __float2bfloat16(b);
    float la = a - __bfloat162float(ha), lb = b - __bfloat162float(hb);
    __nv_bfloat162 th; th.x = ha; th.y = hb;
    hw[p] = *reinterpret_cast<uint32_t*>(&th);
    lw[p] = packbf2(la, lb);
  }
  reinterpret_cast<uint2*>(hi)[i] = make_uint2(hw[0], hw[1]);
  reinterpret_cast<uint2*>(lo)[i] = make_uint2(lw[0], lw[1]);
}

// ---------------- fused attention ----------------
__global__ __launch_bounds__(THREADS, 1) void attn_hmma_kernel(float* __restrict__ out,
                                                               float* __restrict__ attn,
                                                               int write_attn) {
  extern __shared__ __align__(1024) char smem[];
  const uint32_t sb = smem_u32(smem);
  float* Lrow = reinterpret_cast<float*>(smem + SM_L);

  const int tid = threadIdx.x, wid = tid >> 5, lane = tid & 31;
  const int bh = blockIdx.y;
  const int mbase = (wid >> 2) * 64;   // warp row: 0 / 64
  const int nbase = (wid & 3) * 32;    // warp col: 0/32/64/96

  const __nv_bfloat16* qh = g_qh + (size_t)bh * Sn * DKn;
  const __nv_bfloat16* ql = g_ql + (size_t)bh * Sn * DKn;
  const __nv_bfloat16* kh = g_kh + (size_t)bh * Sn * DKn;
  const __nv_bfloat16* kl = g_kl + (size_t)bh * Sn * DKn;
  const __nv_bfloat16* vh = g_vh + (size_t)bh * Sn * DKn;
  const __nv_bfloat16* vl = g_vl + (size_t)bh * Sn * DKn;

  for (int half = 0; half < 2; ++half) {
    const int it = half ? (NT - 1 - (int)blockIdx.x) : (int)blockIdx.x;
    const int qrow0 = it * 128;

    load_tile(qh + (size_t)qrow0 * DKn, sb + SM_QH, tid);
    load_tile(ql + (size_t)qrow0 * DKn, sb + SM_QL, tid);
    cp_commit();
    if (tid < 128) Lrow[tid] = 0.0f;

    float o[16][4];
#pragma unroll
    for (int f = 0; f < 16; ++f)
#pragma unroll
      for (int x = 0; x < 4; ++x) o[f][x] = 0.0f;
    float lsum[4][2] = {};

    for (int jt = 0; jt <= it; ++jt) {
      load_tile(kh + (size_t)jt * 128 * DKn, sb + SM_KVH, tid);
      load_tile(kl + (size_t)jt * 128 * DKn, sb + SM_KVL, tid);
      cp_commit();
      cp_wait0();
      __syncthreads();

      // ---- S = Q K^T (hi*hi + hi*lo + lo*hi) ----
      float s[16][4];
#pragma unroll
      for (int f = 0; f < 16; ++f)
#pragma unroll
        for (int x = 0; x < 4; ++x) s[f][x] = 0.0f;

#pragma unroll
      for (int ks2 = 0; ks2 < 4; ++ks2) {
        const int k0 = ks2 * 32;
        uint32_t bh_[4][4], bl_[4][4];
#pragma unroll
        for (int nt = 0; nt < 4; ++nt) {
          uint32_t off = tile_off(nbase + 8 * nt + (lane & 7), k0 + ((lane >> 3) << 3));
          ldsm4(sb + SM_KVH + off, bh_[nt]);
          ldsm4(sb + SM_KVL + off, bl_[nt]);
        }
#pragma unroll
        for (int mt = 0; mt < 4; ++mt) {
#pragma unroll
          for (int sub = 0; sub < 2; ++sub) {
            uint32_t ah[4], al[4];
            uint32_t off =
                tile_off(mbase + 16 * mt + (lane & 15), k0 + 16 * sub + ((lane >> 4) << 3));
            ldsm4(sb + SM_QH + off, ah);
            ldsm4(sb + SM_QL + off, al);
#pragma unroll
            for (int nt = 0; nt < 4; ++nt) {
              float* sf = s[mt * 4 + nt];
              mma16816(sf, ah, &bh_[nt][2 * sub]);
              mma16816(sf, ah, &bl_[nt][2 * sub]);
              mma16816(sf, al, &bh_[nt][2 * sub]);
            }
          }
        }
      }
      __syncthreads();  // all K reads done -> reuse KV buffer for V

      load_tile(vh + (size_t)jt * 128 * DKn, sb + SM_KVH, tid);
      load_tile(vl + (size_t)jt * 128 * DKn, sb + SM_KVL, tid);
      cp_commit();  // overlaps epilogue

      // ---- epilogue: exp, mask, rowsum, attn write, P pack ----
      const bool diag = (jt == it);
      const int cb = nbase + 2 * (lane & 3);
#pragma unroll
      for (int mt = 0; mt < 4; ++mt) {
        const int rlo = mbase + 16 * mt + (lane >> 2);
        const int rhi = rlo + 8;
        const int glo = qrow0 + rlo, ghi = qrow0 + rhi;
#pragma unroll
        for (int nt = 0; nt < 4; ++nt) {
          float* sf = s[mt * 4 + nt];
          const int c = cb + 8 * nt;
          const int jc = jt * 128 + c;
          float e0 = __expf(sf[0] * SCALE);
          float e1 = __expf(sf[1] * SCALE);
          float e2 = __expf(sf[2] * SCALE);
          float e3 = __expf(sf[3] * SCALE);
          if (diag) {
            if (jc > glo) e0 = 0.0f;
            if (jc + 1 > glo) e1 = 0.0f;
            if (jc > ghi) e2 = 0.0f;
            if (jc + 1 > ghi) e3 = 0.0f;
          }
          lsum[mt][0] += e0 + e1;
          lsum[mt][1] += e2 + e3;
          if (write_attn) {
            *reinterpret_cast<float2*>(attn + ((size_t)bh * Sn + glo) * Sn + jc) =
                make_float2(e0, e1);
            *reinterpret_cast<float2*>(attn + ((size_t)bh * Sn + ghi) * Sn + jc) =
                make_float2(e2, e3);
          }
          // pack to bf16 hi/lo into P tiles
          __nv_bfloat16 h0 = __float2bfloat16(e0), h1 = __float2bfloat16(e1);
          __nv_bfloat16 h2 = __float2bfloat16(e2), h3 = __float2bfloat16(e3);
          __nv_bfloat162 ph01; ph01.x = h0; ph01.y = h1;
          __nv_bfloat162 ph23; ph23.x = h2; ph23.y = h3;
          uint32_t pl01 = packbf2(e0 - __bfloat162float(h0), e1 - __bfloat162float(h1));
          uint32_t pl23 = packbf2(e2 - __bfloat162float(h2), e3 - __bfloat162float(h3));
          uint32_t olo = tile_off(rlo, c), ohi = tile_off(rhi, c);
          *reinterpret_cast<uint32_t*>(smem + SM_PH + olo) = *reinterpret_cast<uint32_t*>(&ph01);
          *reinterpret_cast<uint32_t*>(smem + SM_PL + olo) = pl01;
          *reinterpret_cast<uint32_t*>(smem + SM_PH + ohi) = *reinterpret_cast<uint32_t*>(&ph23);
          *reinterpret_cast<uint32_t*>(smem + SM_PL + ohi) = pl23;
        }
      }
      cp_wait0();
      __syncthreads();  // V ready, P visible

      // ---- O += P V ----
#pragma unroll
      for (int ks2 = 0; ks2 < 4; ++ks2) {
        const int k0 = ks2 * 32;
        uint32_t bh_[4][4], bl_[4][4];
#pragma unroll
        for (int nt = 0; nt < 4; ++nt) {
          uint32_t off = tile_off(k0 + lane, nbase + 8 * nt);
          ldsm4t(sb + SM_KVH + off, bh_[nt]);
          ldsm4t(sb + SM_KVL + off, bl_[nt]);
        }
#pragma unroll
        for (int mt = 0; mt < 4; ++mt) {
#pragma unroll
          for (int sub = 0; sub < 2; ++sub) {
            uint32_t ah[4], al[4];
            uint32_t off =
                tile_off(mbase + 16 * mt + (lane & 15), k0 + 16 * sub + ((lane >> 4) << 3));
            ldsm4(sb + SM_PH + off, ah);
            ldsm4(sb + SM_PL + off, al);
#pragma unroll
            for (int nt = 0; nt < 4; ++nt) {
              float* of = o[mt * 4 + nt];
              mma16816(of, ah, &bh_[nt][2 * sub]);
              mma16816(of, ah, &bl_[nt][2 * sub]);
              mma16816(of, al, &bh_[nt][2 * sub]);
            }
          }
        }
      }
      __syncthreads();  // P/V reads done before next jt overwrites
    }  // jt

    // ---- rowsum reduce + normalize + store ----
#pragma unroll
    for (int mt = 0; mt < 4; ++mt)
#pragma unroll
      for (int h = 0; h < 2; ++h) {
        float v = lsum[mt][h];
        v += __shfl_xor_sync(0xFFFFFFFFu, v, 1);
        v += __shfl_xor_sync(0xFFFFFFFFu, v, 2);
        if ((lane & 3) == 0)
          atomicAdd(&Lrow[mbase + 16 * mt + (lane >> 2) + 8 * h], v);
      }
    __syncthreads();

    if (tid < 128) g_L[(size_t)bh * Sn + qrow0 + tid] = Lrow[tid];

    const int cb = nbase + 2 * (lane & 3);
#pragma unroll
    for (int mt = 0; mt < 4; ++mt) {
      const int rlo = mbase + 16 * mt + (lane >> 2);
      const int rhi = rlo + 8;
      const float ilo = 1.0f / Lrow[rlo], ihi = 1.0f / Lrow[rhi];
#pragma unroll
      for (int nt = 0; nt < 4; ++nt) {
        float* of = o[mt * 4 + nt];
        const int c = cb + 8 * nt;
        *reinterpret_cast<float2*>(out + ((size_t)bh * Sn + qrow0 + rlo) * DKn + c) =
            make_float2(of[0] * ilo, of[1] * ilo);
        *reinterpret_cast<float2*>(out + ((size_t)bh * Sn + qrow0 + rhi) * DKn + c) =
            make_float2(of[2] * ihi, of[3] * ihi);
      }
    }
    __syncthreads();  // Lrow reads done before next half zeroes it
  }  // half
}

// ---------------- attn normalization ----------------
__global__ __launch_bounds__(256) void norm_attn_kernel(float* __restrict__ attn) {
  const int bh = blockIdx.z;
  const int row = blockIdx.y;
  const int c4 = blockIdx.x * 256 + threadIdx.x;
  const int col = c4 * 4;
  float4* p = (float4*)(attn + ((size_t)bh * Sn + row) * Sn) + c4;
  if (col > row) { *p = make_float4(0.f, 0.f, 0.f, 0.f); return; }
  const float inv = 1.0f / g_L[(size_t)bh * Sn + row];
  float4 a = *p;
  if (col + 3 <= row) {
    a.x *= inv; a.y *= inv; a.z *= inv; a.w *= inv;
  } else {
    a.x = (col + 0 <= row) ? a.x * inv : 0.f;
    a.y = (col + 1 <= row) ? a.y * inv : 0.f;
    a.z = (col + 2 <= row) ? a.z * inv : 0.f;
    a.w = (col + 3 <= row) ? a.w * inv : 0.f;
  }
  *p = a;
}

extern "C" void kernel_launch(void* const* d_in, const int* in_sizes, int n_in,
                              void* d_out, int out_size) {
  const float* q = (const float*)d_in[0];
  const float* k = (const float*)d_in[1];
  const float* v = (const float*)d_in[2];
  (void)in_sizes; (void)n_in;  // d_in[3] = tril mask, implied by col<=row

  float* out = (float*)d_out;
  const long long OUT_ELEMS = (long long)BHn * Sn * DKn;
  const long long ATTN_ELEMS = (long long)BHn * Sn * Sn;
  float* attn = nullptr;
  int write_attn = 0;
  if ((long long)out_size >= OUT_ELEMS + ATTN_ELEMS) {
    attn = out + OUT_ELEMS;
    write_attn = 1;
  }

  const int n4 = (int)(OUT_ELEMS / 4);
  split_kernel<<<n4 / 256, 256>>>(q, 0);
  split_kernel<<<n4 / 256, 256>>>(k, 1);
  split_kernel<<<n4 / 256, 256>>>(v, 2);

  cudaFuncSetAttribute(attn_hmma_kernel, cudaFuncAttributeMaxDynamicSharedMemorySize, SMEM_TOTAL);
  attn_hmma_kernel<<<dim3(NT / 2, BHn), THREADS, SMEM_TOTAL>>>(out, attn, write_attn);

  if (write_attn) {
    norm_attn_kernel<<<dim3(Sn / (4 * 256), Sn, BHn), 256>>>(attn);
  }
}